// round 8
// baseline (speedup 1.0000x reference)
#include <cuda_runtime.h>
#include <math.h>

#define NN 1024
#define HEADS 8
#define DKk 16
#define EDIM 16

// -------- device scratch (allocation-free) --------
__device__ float g_q[NN*128];
__device__ float g_k[NN*128];
__device__ float g_v[NN*128];
__device__ float g_W[(size_t)HEADS*NN*NN];   // [h][n][m], unnormalized masked exp weights
__device__ float g_S[NN*128];                // [n][h*16+e]
__device__ float g_den[NN*HEADS];
__device__ float g_av[NN*128];               // sum_m w*v (pre-normalization)

// ================= A: LayerNorm + QKV (4 nodes / block) =================
__global__ __launch_bounds__(128) void k_qkv(
    const float* __restrict__ x,
    const float* __restrict__ Wq, const float* __restrict__ bq,
    const float* __restrict__ Wk, const float* __restrict__ bk,
    const float* __restrict__ Wv, const float* __restrict__ bv,
    const float* __restrict__ gamma, const float* __restrict__ beta)
{
    __shared__ float hs[4][128];
    int n0 = blockIdx.x * 4;
    int w = threadIdx.x >> 5, lane = threadIdx.x & 31;

    // each warp normalizes one node
    const float4* xr = (const float4*)(x + (size_t)(n0 + w) * 128);
    float4 xa = xr[lane];
    float s  = xa.x + xa.y + xa.z + xa.w;
    float s2 = xa.x*xa.x + xa.y*xa.y + xa.z*xa.z + xa.w*xa.w;
    #pragma unroll
    for (int o = 16; o; o >>= 1) {
        s  += __shfl_xor_sync(0xffffffffu, s,  o);
        s2 += __shfl_xor_sync(0xffffffffu, s2, o);
    }
    float mu  = s * (1.0f / 128.0f);
    float var = s2 * (1.0f / 128.0f) - mu * mu;
    float rs  = rsqrtf(var + 1e-5f);
    float4 gv = ((const float4*)gamma)[lane];
    float4 bv4 = ((const float4*)beta)[lane];
    float4 hv;
    hv.x = (xa.x - mu) * rs * gv.x + bv4.x;
    hv.y = (xa.y - mu) * rs * gv.y + bv4.y;
    hv.z = (xa.z - mu) * rs * gv.z + bv4.z;
    hv.w = (xa.w - mu) * rs * gv.w + bv4.w;
    ((float4*)hs[w])[lane] = hv;
    __syncthreads();

    int c = threadIdx.x;
    float aq0 = bq[c], aq1 = aq0, aq2 = aq0, aq3 = aq0;
    float ak0 = bk[c], ak1 = ak0, ak2 = ak0, ak3 = ak0;
    float av0 = bv[c], av1 = av0, av2 = av0, av3 = av0;
    #pragma unroll 4
    for (int j = 0; j < 128; j++) {
        float wq = Wq[j*128 + c], wk = Wk[j*128 + c], wv = Wv[j*128 + c];
        float h0 = hs[0][j], h1 = hs[1][j], h2 = hs[2][j], h3 = hs[3][j];
        aq0 += h0*wq; aq1 += h1*wq; aq2 += h2*wq; aq3 += h3*wq;
        ak0 += h0*wk; ak1 += h1*wk; ak2 += h2*wk; ak3 += h3*wk;
        av0 += h0*wv; av1 += h1*wv; av2 += h2*wv; av3 += h3*wv;
    }
    // pre-scale q by 1/sqrt(dk) = 0.25
    g_q[(size_t)(n0+0)*128 + c] = aq0 * 0.25f;
    g_q[(size_t)(n0+1)*128 + c] = aq1 * 0.25f;
    g_q[(size_t)(n0+2)*128 + c] = aq2 * 0.25f;
    g_q[(size_t)(n0+3)*128 + c] = aq3 * 0.25f;
    g_k[(size_t)(n0+0)*128 + c] = ak0;
    g_k[(size_t)(n0+1)*128 + c] = ak1;
    g_k[(size_t)(n0+2)*128 + c] = ak2;
    g_k[(size_t)(n0+3)*128 + c] = ak3;
    g_v[(size_t)(n0+0)*128 + c] = av0;
    g_v[(size_t)(n0+1)*128 + c] = av1;
    g_v[(size_t)(n0+2)*128 + c] = av2;
    g_v[(size_t)(n0+3)*128 + c] = av3;
}

// ================= B: logits + bias + mask + exp -> g_W =================
// grid (16,16): 64m x 64n tile. 256 threads: nl=tid>>4 (n = n0+nl+i*16),
// ml=tid&15 (m = m0+ml+j*16). Per-thread 4n x 4m x 8h.
__global__ __launch_bounds__(256, 1) void k_logits(
    const float* __restrict__ edge, const int* __restrict__ mask,
    const float* __restrict__ Wae, const float* __restrict__ bae)
{
    __shared__ float waeS[EDIM * HEADS];   // [e*8+h]
    __shared__ float baeS[8];
    __shared__ float qs[64 * 17];
    __shared__ float ks[64 * 17];
    int tid = threadIdx.x;
    if (tid < 128) waeS[tid] = Wae[tid];
    if (tid < 8)   baeS[tid] = bae[tid];
    __syncthreads();

    int n0 = blockIdx.y * 64, m0 = blockIdx.x * 64;
    int nl = tid >> 4, ml = tid & 15;

    float bias[4][4][8];
    #pragma unroll
    for (int i = 0; i < 4; i++)
        #pragma unroll
        for (int j = 0; j < 4; j++)
            #pragma unroll
            for (int h = 0; h < 8; h++) bias[i][j][h] = baeS[h];

    unsigned mbits = 0;
    const float4* wa4 = (const float4*)waeS;
    #pragma unroll
    for (int i = 0; i < 4; i++) {
        #pragma unroll
        for (int j = 0; j < 4; j++) {
            int nn = n0 + nl + i*16, mm = m0 + ml + j*16;
            const float4* ep = (const float4*)(edge + ((size_t)nn*NN + mm) * EDIM);
            float4 e0 = ep[0], e1 = ep[1], e2 = ep[2], e3 = ep[3];
            if (mask[(size_t)nn*NN + mm]) mbits |= 1u << (i*4 + j);
            float ev[16] = { e0.x,e0.y,e0.z,e0.w, e1.x,e1.y,e1.z,e1.w,
                             e2.x,e2.y,e2.z,e2.w, e3.x,e3.y,e3.z,e3.w };
            #pragma unroll
            for (int e = 0; e < 16; e++) {
                float t = ev[e];
                float4 a = wa4[e*2], b = wa4[e*2 + 1];
                bias[i][j][0] += t*a.x; bias[i][j][1] += t*a.y;
                bias[i][j][2] += t*a.z; bias[i][j][3] += t*a.w;
                bias[i][j][4] += t*b.x; bias[i][j][5] += t*b.y;
                bias[i][j][6] += t*b.z; bias[i][j][7] += t*b.w;
            }
        }
    }

    #pragma unroll
    for (int h = 0; h < 8; h++) {
        __syncthreads();
        {   // stage this head's q/k slices (64x16 each), stride-17 smem
            int r = tid >> 2, c4 = tid & 3;
            float4 qv = *(const float4*)(g_q + (size_t)(n0 + r)*128 + h*16 + c4*4);
            float4 kv = *(const float4*)(g_k + (size_t)(m0 + r)*128 + h*16 + c4*4);
            float* qd = qs + r*17 + c4*4;
            qd[0]=qv.x; qd[1]=qv.y; qd[2]=qv.z; qd[3]=qv.w;
            float* kd = ks + r*17 + c4*4;
            kd[0]=kv.x; kd[1]=kv.y; kd[2]=kv.z; kd[3]=kv.w;
        }
        __syncthreads();
        float kreg[4][16];
        #pragma unroll
        for (int j = 0; j < 4; j++)
            #pragma unroll
            for (int kk = 0; kk < 16; kk++)
                kreg[j][kk] = ks[(ml + j*16)*17 + kk];
        #pragma unroll
        for (int i = 0; i < 4; i++) {
            float qreg[16];
            #pragma unroll
            for (int kk = 0; kk < 16; kk++) qreg[kk] = qs[(nl + i*16)*17 + kk];
            #pragma unroll
            for (int j = 0; j < 4; j++) {
                float acc = bias[i][j][h];
                #pragma unroll
                for (int kk = 0; kk < 16; kk++) acc += qreg[kk] * kreg[j][kk];
                float wv = ((mbits >> (i*4 + j)) & 1u) ? __expf(acc) : 0.0f;
                g_W[((size_t)h << 20) + (size_t)(n0 + nl + i*16)*NN + (m0 + ml + j*16)] = wv;
            }
        }
    }
}

// ================= C: S[n,h,e] = sum_m w*edge,  den[n,h] = sum_m w ======
// grid 256 (4 nodes / block), 128 threads: e4=tid&3, h=(tid>>2)&7, nl=tid>>5
__global__ __launch_bounds__(128) void k_S(const float* __restrict__ edge)
{
    __shared__ float4 es[4][64][4];     // [nl][m][e-quad]
    __shared__ float  ws[4][8][68];     // padded: h-stride 68 -> conflict-free
    int tid = threadIdx.x;
    int n_base = blockIdx.x * 4;
    int e4 = tid & 3, h = (tid >> 2) & 7, nl = tid >> 5;
    float a0 = 0, a1 = 0, a2 = 0, a3 = 0, den = 0;

    for (int ch = 0; ch < 16; ch++) {
        int m0 = ch * 64;
        __syncthreads();
        #pragma unroll
        for (int u = 0; u < 8; u++) {
            int idx = tid + u*128;            // 1024 float4s of edge chunk
            int nn = idx >> 8, rest = idx & 255;
            es[nn][rest >> 2][rest & 3] =
                ((const float4*)(edge + (size_t)(n_base + nn)*NN*EDIM))[m0*4 + rest];
        }
        #pragma unroll
        for (int u = 0; u < 4; u++) {
            int idx = tid + u*128;            // 512 float4s of W chunk
            int nn = idx >> 7, rest = idx & 127;
            int hh = rest >> 4, m4 = rest & 15;
            float4 wv = *(const float4*)(g_W + ((size_t)hh << 20)
                         + (size_t)(n_base + nn)*NN + m0 + m4*4);
            float* d = &ws[nn][hh][m4*4];
            d[0]=wv.x; d[1]=wv.y; d[2]=wv.z; d[3]=wv.w;
        }
        __syncthreads();
        #pragma unroll 4
        for (int mm = 0; mm < 64; mm++) {
            float w = ws[nl][h][mm];
            float4 ev = es[nl][mm][e4];
            a0 += w*ev.x; a1 += w*ev.y; a2 += w*ev.z; a3 += w*ev.w;
            if (e4 == 0) den += w;
        }
    }
    *(float4*)(g_S + (size_t)(n_base + nl)*128 + h*16 + e4*4) = make_float4(a0, a1, a2, a3);
    if (e4 == 0) g_den[(n_base + nl)*8 + h] = den;
}

// ================= D: g_av[n,h,d] = sum_m w[h,n,m]*v[m,h,d] =============
// grid 256: h = b&7, n-tile of 32 = b>>3. 128 threads: dl=tid&7 (2 d), nl=tid>>3 (2 n)
__global__ __launch_bounds__(128) void k_av()
{
    __shared__ float wsD[32][129];
    __shared__ float vsD[128][16];
    int h = blockIdx.x & 7, n0 = (blockIdx.x >> 3) * 32;
    int tid = threadIdx.x;
    int dl = tid & 7, nl = tid >> 3;
    float acc00 = 0, acc01 = 0, acc10 = 0, acc11 = 0;

    for (int ch = 0; ch < 8; ch++) {
        int m0 = ch * 128;
        __syncthreads();
        #pragma unroll
        for (int u = 0; u < 8; u++) {
            int idx = tid + u*128;            // 1024 float4s of W (32x128)
            int row = idx >> 5, c4 = idx & 31;
            float4 wv = *(const float4*)(g_W + ((size_t)h << 20)
                         + (size_t)(n0 + row)*NN + m0 + c4*4);
            float* d = &wsD[row][c4*4];
            d[0]=wv.x; d[1]=wv.y; d[2]=wv.z; d[3]=wv.w;
        }
        #pragma unroll
        for (int u = 0; u < 4; u++) {
            int idx = tid + u*128;            // 512 float4s of v (128x16)
            int row = idx >> 2, c4 = idx & 3;
            *(float4*)(&vsD[row][c4*4]) =
                *(const float4*)(g_v + (size_t)(m0 + row)*128 + h*16 + c4*4);
        }
        __syncthreads();
        #pragma unroll 4
        for (int mm = 0; mm < 128; mm++) {
            float2 vv = *(const float2*)(&vsD[mm][dl*2]);
            float w0 = wsD[nl*2 + 0][mm];
            float w1 = wsD[nl*2 + 1][mm];
            acc00 += w0*vv.x; acc01 += w0*vv.y;
            acc10 += w1*vv.x; acc11 += w1*vv.y;
        }
    }
    *(float2*)(g_av + (size_t)(n0 + nl*2 + 0)*128 + h*16 + dl*2) = make_float2(acc00, acc01);
    *(float2*)(g_av + (size_t)(n0 + nl*2 + 1)*128 + h*16 + dl*2) = make_float2(acc10, acc11);
}

// ================= E: edge term + normalize + Wo + residual =============
__global__ __launch_bounds__(128) void k_out(
    const float* __restrict__ x,
    const float* __restrict__ Wve, const float* __restrict__ bve,
    const float* __restrict__ Wo, const float* __restrict__ bo,
    float* __restrict__ out)
{
    __shared__ float Ss[128], attS[128], denS[8];
    int n = blockIdx.x, c = threadIdx.x, h = c >> 4;
    Ss[c] = g_S[(size_t)n*128 + c];
    if (c < 8) denS[c] = g_den[n*8 + c];
    __syncthreads();
    float acc = g_av[(size_t)n*128 + c];
    #pragma unroll
    for (int e = 0; e < 16; e++) acc += Ss[h*16 + e] * Wve[e*128 + c];
    float att = acc / denS[h] + bve[c];
    attS[c] = att;
    __syncthreads();
    float o = bo[c];
    #pragma unroll 8
    for (int j = 0; j < 128; j++) o += attS[j] * Wo[j*128 + c];
    out[(size_t)n*128 + c] = x[(size_t)n*128 + c] + o;
}

// ================= launcher =================
extern "C" void kernel_launch(void* const* d_in, const int* in_sizes, int n_in,
                              void* d_out, int out_size)
{
    const float* x     = (const float*)d_in[0];
    const float* edge  = (const float*)d_in[1];
    const int*   mask  = (const int*)  d_in[2];
    const float* Wq    = (const float*)d_in[3];
    const float* bq    = (const float*)d_in[4];
    const float* Wk    = (const float*)d_in[5];
    const float* bk    = (const float*)d_in[6];
    const float* Wv    = (const float*)d_in[7];
    const float* bv    = (const float*)d_in[8];
    const float* Wae   = (const float*)d_in[9];
    const float* bae   = (const float*)d_in[10];
    const float* Wve   = (const float*)d_in[11];
    const float* bve   = (const float*)d_in[12];
    const float* Wo    = (const float*)d_in[13];
    const float* bo    = (const float*)d_in[14];
    const float* gamma = (const float*)d_in[15];
    const float* beta  = (const float*)d_in[16];
    float* out = (float*)d_out;

    k_qkv<<<256, 128>>>(x, Wq, bq, Wk, bk, Wv, bv, gamma, beta);
    dim3 gb(16, 16);
    k_logits<<<gb, 256>>>(edge, mask, Wae, bae);
    k_S<<<256, 128>>>(edge);
    k_av<<<256, 128>>>();
    k_out<<<1024, 128>>>(x, Wve, bve, Wo, bo, out);
}

// round 10
// speedup vs baseline: 1.0435x; 1.0435x over previous
#include <cuda_runtime.h>
#include <math.h>

#define NN 1024
#define HEADS 8
#define EDIM 16

// -------- device scratch (allocation-free) --------
__device__ float g_q[NN*128];
__device__ float g_k[NN*128];
__device__ float g_v[NN*128];
__device__ float g_W[(size_t)HEADS*NN*NN];   // [h][n][m] unnormalized masked exp weights
__device__ float g_S [NN*128];               // partial S (m half 0)
__device__ float g_S2[NN*128];               // partial S (m half 1)
__device__ float g_den [NN*HEADS];
__device__ float g_den2[NN*HEADS];
__device__ float g_av [NN*128];
__device__ float g_av2[NN*128];

// ================= A: LayerNorm + QKV (4 nodes / block) =================
__global__ __launch_bounds__(128) void k_qkv(
    const float* __restrict__ x,
    const float* __restrict__ Wq, const float* __restrict__ bq,
    const float* __restrict__ Wk, const float* __restrict__ bk,
    const float* __restrict__ Wv, const float* __restrict__ bv,
    const float* __restrict__ gamma, const float* __restrict__ beta)
{
    __shared__ float hs[4][128];
    int n0 = blockIdx.x * 4;
    int w = threadIdx.x >> 5, lane = threadIdx.x & 31;

    const float4* xr = (const float4*)(x + (size_t)(n0 + w) * 128);
    float4 xa = xr[lane];
    float s  = xa.x + xa.y + xa.z + xa.w;
    float s2 = xa.x*xa.x + xa.y*xa.y + xa.z*xa.z + xa.w*xa.w;
    #pragma unroll
    for (int o = 16; o; o >>= 1) {
        s  += __shfl_xor_sync(0xffffffffu, s,  o);
        s2 += __shfl_xor_sync(0xffffffffu, s2, o);
    }
    float mu  = s * (1.0f / 128.0f);
    float var = s2 * (1.0f / 128.0f) - mu * mu;
    float rs  = rsqrtf(var + 1e-5f);
    float4 gv = ((const float4*)gamma)[lane];
    float4 bv4 = ((const float4*)beta)[lane];
    float4 hv;
    hv.x = (xa.x - mu) * rs * gv.x + bv4.x;
    hv.y = (xa.y - mu) * rs * gv.y + bv4.y;
    hv.z = (xa.z - mu) * rs * gv.z + bv4.z;
    hv.w = (xa.w - mu) * rs * gv.w + bv4.w;
    ((float4*)hs[w])[lane] = hv;
    __syncthreads();

    int c = threadIdx.x;
    float aq0 = bq[c], aq1 = aq0, aq2 = aq0, aq3 = aq0;
    float ak0 = bk[c], ak1 = ak0, ak2 = ak0, ak3 = ak0;
    float av0 = bv[c], av1 = av0, av2 = av0, av3 = av0;
    #pragma unroll 4
    for (int j = 0; j < 128; j++) {
        float wq = Wq[j*128 + c], wk = Wk[j*128 + c], wv = Wv[j*128 + c];
        float h0 = hs[0][j], h1 = hs[1][j], h2 = hs[2][j], h3 = hs[3][j];
        aq0 += h0*wq; aq1 += h1*wq; aq2 += h2*wq; aq3 += h3*wq;
        ak0 += h0*wk; ak1 += h1*wk; ak2 += h2*wk; ak3 += h3*wk;
        av0 += h0*wv; av1 += h1*wv; av2 += h2*wv; av3 += h3*wv;
    }
    g_q[(size_t)(n0+0)*128 + c] = aq0 * 0.25f;   // pre-scale 1/sqrt(16)
    g_q[(size_t)(n0+1)*128 + c] = aq1 * 0.25f;
    g_q[(size_t)(n0+2)*128 + c] = aq2 * 0.25f;
    g_q[(size_t)(n0+3)*128 + c] = aq3 * 0.25f;
    g_k[(size_t)(n0+0)*128 + c] = ak0;
    g_k[(size_t)(n0+1)*128 + c] = ak1;
    g_k[(size_t)(n0+2)*128 + c] = ak2;
    g_k[(size_t)(n0+3)*128 + c] = ak3;
    g_v[(size_t)(n0+0)*128 + c] = av0;
    g_v[(size_t)(n0+1)*128 + c] = av1;
    g_v[(size_t)(n0+2)*128 + c] = av2;
    g_v[(size_t)(n0+3)*128 + c] = av3;
}

// ================= B: logits + bias + mask + exp -> g_W =================
// 32n x 32m tile, grid (32,32), 256 threads. Thread: nl=tid>>4, ml=tid&15.
// Per-thread 2n x 2m x 8h. ~120 regs -> 2 blocks/SM.
__global__ __launch_bounds__(256, 2) void k_logits(
    const float* __restrict__ edge, const int* __restrict__ mask,
    const float* __restrict__ Wae, const float* __restrict__ bae)
{
    __shared__ float waeS[128];          // [e*8+h]
    __shared__ float baeS[8];
    __shared__ float qs[32*17];
    __shared__ float ks[32*17];
    int tid = threadIdx.x;
    if (tid < 128) waeS[tid] = Wae[tid];
    if (tid < 8)   baeS[tid] = bae[tid];
    __syncthreads();

    int n0 = blockIdx.y * 32, m0 = blockIdx.x * 32;
    int nl = tid >> 4, ml = tid & 15;

    float bias[2][2][8];
    #pragma unroll
    for (int i = 0; i < 2; i++)
        #pragma unroll
        for (int j = 0; j < 2; j++)
            #pragma unroll
            for (int h = 0; h < 8; h++) bias[i][j][h] = baeS[h];

    unsigned mbits = 0;
    const float4* wa4 = (const float4*)waeS;
    #pragma unroll
    for (int i = 0; i < 2; i++) {
        #pragma unroll
        for (int j = 0; j < 2; j++) {
            int nn = n0 + nl + i*16, mm = m0 + ml + j*16;
            const float4* ep = (const float4*)(edge + ((size_t)nn*NN + mm) * EDIM);
            float4 e0 = ep[0], e1 = ep[1], e2 = ep[2], e3 = ep[3];
            if (mask[(size_t)nn*NN + mm]) mbits |= 1u << (i*2 + j);
            float ev[16] = { e0.x,e0.y,e0.z,e0.w, e1.x,e1.y,e1.z,e1.w,
                             e2.x,e2.y,e2.z,e2.w, e3.x,e3.y,e3.z,e3.w };
            #pragma unroll
            for (int e = 0; e < 16; e++) {
                float t = ev[e];
                float4 a = wa4[e*2], b = wa4[e*2 + 1];
                bias[i][j][0] += t*a.x; bias[i][j][1] += t*a.y;
                bias[i][j][2] += t*a.z; bias[i][j][3] += t*a.w;
                bias[i][j][4] += t*b.x; bias[i][j][5] += t*b.y;
                bias[i][j][6] += t*b.z; bias[i][j][7] += t*b.w;
            }
        }
    }

    #pragma unroll
    for (int h = 0; h < 8; h++) {
        __syncthreads();
        if (tid < 128) {                       // stage q slice 32x16, stride 17
            int r = tid >> 2, c4 = tid & 3;
            float4 qv = *(const float4*)(g_q + (size_t)(n0 + r)*128 + h*16 + c4*4);
            float* qd = qs + r*17 + c4*4;
            qd[0]=qv.x; qd[1]=qv.y; qd[2]=qv.z; qd[3]=qv.w;
        } else {                               // stage k slice 32x16, stride 17
            int t = tid - 128;
            int r = t >> 2, c4 = t & 3;
            float4 kv = *(const float4*)(g_k + (size_t)(m0 + r)*128 + h*16 + c4*4);
            float* kd = ks + r*17 + c4*4;
            kd[0]=kv.x; kd[1]=kv.y; kd[2]=kv.z; kd[3]=kv.w;
        }
        __syncthreads();
        float kreg[2][16];
        #pragma unroll
        for (int j = 0; j < 2; j++)
            #pragma unroll
            for (int kk = 0; kk < 16; kk++)
                kreg[j][kk] = ks[(ml + j*16)*17 + kk];
        #pragma unroll
        for (int i = 0; i < 2; i++) {
            float qreg[16];
            #pragma unroll
            for (int kk = 0; kk < 16; kk++) qreg[kk] = qs[(nl + i*16)*17 + kk];
            #pragma unroll
            for (int j = 0; j < 2; j++) {
                float acc = bias[i][j][h];
                #pragma unroll
                for (int kk = 0; kk < 16; kk++) acc += qreg[kk] * kreg[j][kk];
                float wv = ((mbits >> (i*2 + j)) & 1u) ? __expf(acc) : 0.0f;
                g_W[((size_t)h << 20) + (size_t)(n0 + nl + i*16)*NN + (m0 + ml + j*16)] = wv;
            }
        }
    }
}

// ================= C: S[n,h,e] = sum_m w*edge, den = sum_m w (m-split 2) ====
// grid 512: nb=b>>1 (4 nodes), half=b&1. 128 threads: e4=tid&3, h=(tid>>2)&7, nl=tid>>5.
// W read via uniform LDG.128 (L1-resident), edge staged in smem.
__global__ __launch_bounds__(128) void k_S(const float* __restrict__ edge)
{
    __shared__ float4 es[4][64][4];     // [nl][m][e-quad]
    int tid = threadIdx.x;
    int n_base = (blockIdx.x >> 1) * 4;
    int half = blockIdx.x & 1;
    int e4 = tid & 3, h = (tid >> 2) & 7, nl = tid >> 5;
    const float* wrow = g_W + ((size_t)h << 20) + (size_t)(n_base + nl) * NN;
    float a0 = 0, a1 = 0, a2 = 0, a3 = 0, den = 0;

    for (int ch = half*8; ch < half*8 + 8; ch++) {
        int m0 = ch * 64;
        __syncthreads();
        #pragma unroll
        for (int u = 0; u < 8; u++) {
            int idx = tid + u*128;
            int nn = idx >> 8, rest = idx & 255;
            es[nn][rest >> 2][rest & 3] =
                ((const float4*)(edge + (size_t)(n_base + nn)*NN*EDIM))[m0*4 + rest];
        }
        __syncthreads();
        #pragma unroll 4
        for (int mm = 0; mm < 64; mm += 4) {
            float4 w4 = *(const float4*)(wrow + m0 + mm);
            float4 ev;
            ev = es[nl][mm+0][e4]; a0 += w4.x*ev.x; a1 += w4.x*ev.y; a2 += w4.x*ev.z; a3 += w4.x*ev.w;
            ev = es[nl][mm+1][e4]; a0 += w4.y*ev.x; a1 += w4.y*ev.y; a2 += w4.y*ev.z; a3 += w4.y*ev.w;
            ev = es[nl][mm+2][e4]; a0 += w4.z*ev.x; a1 += w4.z*ev.y; a2 += w4.z*ev.z; a3 += w4.z*ev.w;
            ev = es[nl][mm+3][e4]; a0 += w4.w*ev.x; a1 += w4.w*ev.y; a2 += w4.w*ev.z; a3 += w4.w*ev.w;
            if (e4 == 0) den += w4.x + w4.y + w4.z + w4.w;
        }
    }
    float* Sp = half ? g_S2  : g_S;
    float* Dp = half ? g_den2 : g_den;
    *(float4*)(Sp + (size_t)(n_base + nl)*128 + h*16 + e4*4) = make_float4(a0, a1, a2, a3);
    if (e4 == 0) Dp[(n_base + nl)*8 + h] = den;
}

// ================= D: av[n,h,d] = sum_m w[h,n,m]*v[m,h,d] (m-split 2) =======
// grid 512: h=b&7, ntile=(b>>3)&31, half=b>>8. 128 threads: dl=tid&3, nl=tid>>2.
// W direct LDG.128 (4 FMA per w component x4), V staged in smem (broadcast LDS.128).
__global__ __launch_bounds__(128) void k_av()
{
    __shared__ float vs[128][16];
    int b = blockIdx.x;
    int h = b & 7, nt = (b >> 3) & 31, half = b >> 8;
    int n0 = nt * 32, mb = half * 512;
    int tid = threadIdx.x;
    int dl = tid & 3, nl = tid >> 2;
    const float* wrow = g_W + ((size_t)h << 20) + (size_t)(n0 + nl) * NN + mb;
    float4 acc = make_float4(0.f, 0.f, 0.f, 0.f);

    for (int ch = 0; ch < 4; ch++) {
        __syncthreads();
        #pragma unroll
        for (int u = 0; u < 4; u++) {
            int idx = tid + u*128;
            int r = idx >> 2, c4 = idx & 3;
            *(float4*)&vs[r][c4*4] =
                *(const float4*)(g_v + (size_t)(mb + ch*128 + r)*128 + h*16 + c4*4);
        }
        __syncthreads();
        #pragma unroll 4
        for (int mm = 0; mm < 128; mm += 4) {
            float4 w4 = *(const float4*)(wrow + ch*128 + mm);
            float4 v0 = *(const float4*)&vs[mm+0][dl*4];
            acc.x += w4.x*v0.x; acc.y += w4.x*v0.y; acc.z += w4.x*v0.z; acc.w += w4.x*v0.w;
            float4 v1 = *(const float4*)&vs[mm+1][dl*4];
            acc.x += w4.y*v1.x; acc.y += w4.y*v1.y; acc.z += w4.y*v1.z; acc.w += w4.y*v1.w;
            float4 v2 = *(const float4*)&vs[mm+2][dl*4];
            acc.x += w4.z*v2.x; acc.y += w4.z*v2.y; acc.z += w4.z*v2.z; acc.w += w4.z*v2.w;
            float4 v3 = *(const float4*)&vs[mm+3][dl*4];
            acc.x += w4.w*v3.x; acc.y += w4.w*v3.y; acc.z += w4.w*v3.z; acc.w += w4.w*v3.w;
        }
    }
    float* P = half ? g_av2 : g_av;
    *(float4*)(P + (size_t)(n0 + nl)*128 + h*16 + dl*4) = acc;
}

// ================= E: edge term + normalize + Wo + residual =============
__global__ __launch_bounds__(128) void k_out(
    const float* __restrict__ x,
    const float* __restrict__ Wve, const float* __restrict__ bve,
    const float* __restrict__ Wo, const float* __restrict__ bo,
    float* __restrict__ out)
{
    __shared__ float Ss[128], attS[128], denS[8];
    int n = blockIdx.x, c = threadIdx.x, h = c >> 4;
    Ss[c] = g_S[(size_t)n*128 + c] + g_S2[(size_t)n*128 + c];
    if (c < 8) denS[c] = g_den[n*8 + c] + g_den2[n*8 + c];
    __syncthreads();
    float acc = g_av[(size_t)n*128 + c] + g_av2[(size_t)n*128 + c];
    #pragma unroll
    for (int e = 0; e < 16; e++) acc += Ss[h*16 + e] * Wve[e*128 + c];
    float att = acc / denS[h] + bve[c];
    attS[c] = att;
    __syncthreads();
    float o = bo[c];
    #pragma unroll 8
    for (int j = 0; j < 128; j++) o += attS[j] * Wo[j*128 + c];
    out[(size_t)n*128 + c] = x[(size_t)n*128 + c] + o;
}

// ================= launcher =================
extern "C" void kernel_launch(void* const* d_in, const int* in_sizes, int n_in,
                              void* d_out, int out_size)
{
    const float* x     = (const float*)d_in[0];
    const float* edge  = (const float*)d_in[1];
    const int*   mask  = (const int*)  d_in[2];
    const float* Wq    = (const float*)d_in[3];
    const float* bq    = (const float*)d_in[4];
    const float* Wk    = (const float*)d_in[5];
    const float* bk    = (const float*)d_in[6];
    const float* Wv    = (const float*)d_in[7];
    const float* bv    = (const float*)d_in[8];
    const float* Wae   = (const float*)d_in[9];
    const float* bae   = (const float*)d_in[10];
    const float* Wve   = (const float*)d_in[11];
    const float* bve   = (const float*)d_in[12];
    const float* Wo    = (const float*)d_in[13];
    const float* bo    = (const float*)d_in[14];
    const float* gamma = (const float*)d_in[15];
    const float* beta  = (const float*)d_in[16];
    float* out = (float*)d_out;

    k_qkv<<<256, 128>>>(x, Wq, bq, Wk, bk, Wv, bv, gamma, beta);
    dim3 gb(32, 32);
    k_logits<<<gb, 256>>>(edge, mask, Wae, bae);
    k_S<<<512, 128>>>(edge);
    k_av<<<512, 128>>>();
    k_out<<<1024, 128>>>(x, Wve, bve, Wo, bo, out);
}

// round 11
// speedup vs baseline: 1.7934x; 1.7187x over previous
#include <cuda_runtime.h>
#include <math.h>

#define NN 1024
#define HEADS 8
#define EDIM 16
#define TN 32          // n-tile per block
#define TM 32          // m chunk staged per iteration
#define MSPLIT 4       // m-range split across blocks
#define CHUNKS 8       // chunks per block: TM*CHUNKS = 256 m

// -------- device scratch (allocation-free) --------
__device__ float g_q[NN*128];
__device__ float g_k[NN*128];
__device__ float g_v[NN*128];
__device__ float g_Sp [MSPLIT*(size_t)NN*128];   // partial S  per m-split
__device__ float g_avp[MSPLIT*(size_t)NN*128];   // partial av per m-split
__device__ float g_dnp[MSPLIT*NN*HEADS];         // partial den

// smem layout (float offsets)
#define K_OFF 0                       // ks[32][164]   (m*164 + h*20 + d)
#define V_OFF 5248                    // vs[32][164]
#define E_OFF 10496                   // es[32 n][516] (n*516 + m*16 + e)
#define M_OFF 27008                   // ms[32 n][33]  ints
#define SM_FLOATS (27008 + 1056)      // 28064 floats = 112256 B

// ================= A: LayerNorm + QKV (4 nodes / block) =================
__global__ __launch_bounds__(128) void k_qkv(
    const float* __restrict__ x,
    const float* __restrict__ Wq, const float* __restrict__ bq,
    const float* __restrict__ Wk, const float* __restrict__ bk,
    const float* __restrict__ Wv, const float* __restrict__ bv,
    const float* __restrict__ gamma, const float* __restrict__ beta)
{
    __shared__ float hs[4][128];
    int n0 = blockIdx.x * 4;
    int w = threadIdx.x >> 5, lane = threadIdx.x & 31;

    const float4* xr = (const float4*)(x + (size_t)(n0 + w) * 128);
    float4 xa = xr[lane];
    float s  = xa.x + xa.y + xa.z + xa.w;
    float s2 = xa.x*xa.x + xa.y*xa.y + xa.z*xa.z + xa.w*xa.w;
    #pragma unroll
    for (int o = 16; o; o >>= 1) {
        s  += __shfl_xor_sync(0xffffffffu, s,  o);
        s2 += __shfl_xor_sync(0xffffffffu, s2, o);
    }
    float mu  = s * (1.0f / 128.0f);
    float var = s2 * (1.0f / 128.0f) - mu * mu;
    float rs  = rsqrtf(var + 1e-5f);
    float4 gv = ((const float4*)gamma)[lane];
    float4 bv4 = ((const float4*)beta)[lane];
    float4 hv;
    hv.x = (xa.x - mu) * rs * gv.x + bv4.x;
    hv.y = (xa.y - mu) * rs * gv.y + bv4.y;
    hv.z = (xa.z - mu) * rs * gv.z + bv4.z;
    hv.w = (xa.w - mu) * rs * gv.w + bv4.w;
    ((float4*)hs[w])[lane] = hv;
    __syncthreads();

    int c = threadIdx.x;
    float aq0 = bq[c], aq1 = aq0, aq2 = aq0, aq3 = aq0;
    float ak0 = bk[c], ak1 = ak0, ak2 = ak0, ak3 = ak0;
    float av0 = bv[c], av1 = av0, av2 = av0, av3 = av0;
    #pragma unroll 4
    for (int j = 0; j < 128; j++) {
        float wq = Wq[j*128 + c], wk = Wk[j*128 + c], wv = Wv[j*128 + c];
        float h0 = hs[0][j], h1 = hs[1][j], h2 = hs[2][j], h3 = hs[3][j];
        aq0 += h0*wq; aq1 += h1*wq; aq2 += h2*wq; aq3 += h3*wq;
        ak0 += h0*wk; ak1 += h1*wk; ak2 += h2*wk; ak3 += h3*wk;
        av0 += h0*wv; av1 += h1*wv; av2 += h2*wv; av3 += h3*wv;
    }
    g_q[(size_t)(n0+0)*128 + c] = aq0 * 0.25f;   // pre-scale 1/sqrt(16)
    g_q[(size_t)(n0+1)*128 + c] = aq1 * 0.25f;
    g_q[(size_t)(n0+2)*128 + c] = aq2 * 0.25f;
    g_q[(size_t)(n0+3)*128 + c] = aq3 * 0.25f;
    g_k[(size_t)(n0+0)*128 + c] = ak0;
    g_k[(size_t)(n0+1)*128 + c] = ak1;
    g_k[(size_t)(n0+2)*128 + c] = ak2;
    g_k[(size_t)(n0+3)*128 + c] = ak3;
    g_v[(size_t)(n0+0)*128 + c] = av0;
    g_v[(size_t)(n0+1)*128 + c] = av1;
    g_v[(size_t)(n0+2)*128 + c] = av2;
    g_v[(size_t)(n0+3)*128 + c] = av3;
}

// ================= FUSED: logits + exp + S/den/av accumulation ==========
// grid 128: bn = b&31 (n-tile of 32), bs = b>>5 (m-split of 256).
// 256 threads: h = tid&7, nl = tid>>3. Thread owns (n, h); w stays in regs.
__global__ __launch_bounds__(256) void k_fused(
    const float* __restrict__ edge, const int* __restrict__ mask,
    const float* __restrict__ Wae, const float* __restrict__ bae)
{
    extern __shared__ float sm[];
    float* ks = sm + K_OFF;
    float* vs = sm + V_OFF;
    float* es = sm + E_OFF;
    int*   ms = (int*)(sm + M_OFF);

    int tid = threadIdx.x;
    int h = tid & 7, nl = tid >> 3;
    int bn = blockIdx.x & 31, bs = blockIdx.x >> 5;
    int n0 = bn * TN;
    int n  = n0 + nl;

    // per-thread constants
    float qr[16];
    {
        const float4* qp = (const float4*)(g_q + (size_t)n*128 + h*16);
        float4 a = qp[0], b = qp[1], c = qp[2], d = qp[3];
        qr[0]=a.x; qr[1]=a.y; qr[2]=a.z; qr[3]=a.w;
        qr[4]=b.x; qr[5]=b.y; qr[6]=b.z; qr[7]=b.w;
        qr[8]=c.x; qr[9]=c.y; qr[10]=c.z; qr[11]=c.w;
        qr[12]=d.x; qr[13]=d.y; qr[14]=d.z; qr[15]=d.w;
    }
    float waeR[16];
    #pragma unroll
    for (int e = 0; e < 16; e++) waeR[e] = Wae[e*8 + h];
    float baeR = bae[h];

    float S[16], av[16], den = 0.f;
    #pragma unroll
    for (int i = 0; i < 16; i++) { S[i] = 0.f; av[i] = 0.f; }

    for (int ch = 0; ch < CHUNKS; ch++) {
        int m0 = bs*256 + ch*TM;
        __syncthreads();
        // stage edge (32n x 32m x 16e), rows contiguous, padded n-stride 516
        #pragma unroll
        for (int i = 0; i < 16; i++) {
            int f = tid + i*256;
            int nn = f >> 7, rem = f & 127;   // 128 float4 per n-row
            float4 val = ((const float4*)(edge + ((size_t)(n0+nn)*NN + m0)*16))[rem];
            *(float4*)(es + nn*516 + rem*4) = val;
        }
        // stage k,v (32m x 128), h-stride 20, m-stride 164 (conflict-free reads)
        #pragma unroll
        for (int i = 0; i < 4; i++) {
            int f = tid + i*256;
            int mm = f >> 5, c4 = f & 31;
            int hh = c4 >> 2, dd = c4 & 3;
            *(float4*)(ks + mm*164 + hh*20 + dd*4) =
                ((const float4*)(g_k + (size_t)(m0+mm)*128))[c4];
            *(float4*)(vs + mm*164 + hh*20 + dd*4) =
                ((const float4*)(g_v + (size_t)(m0+mm)*128))[c4];
        }
        // stage mask
        #pragma unroll
        for (int i = 0; i < 4; i++) {
            int f = tid + i*256;
            int nn = f >> 5, mm = f & 31;
            ms[nn*33 + mm] = mask[(size_t)(n0+nn)*NN + m0 + mm];
        }
        __syncthreads();

        const float* ep_base = es + nl*516;
        const int*   mrow    = ms + nl*33;
        #pragma unroll 2
        for (int m = 0; m < TM; m++) {
            float ev[16], kv[16];
            {
                const float4* ep = (const float4*)(ep_base + m*16);
                float4 a = ep[0], b = ep[1], c = ep[2], d = ep[3];
                ev[0]=a.x; ev[1]=a.y; ev[2]=a.z; ev[3]=a.w;
                ev[4]=b.x; ev[5]=b.y; ev[6]=b.z; ev[7]=b.w;
                ev[8]=c.x; ev[9]=c.y; ev[10]=c.z; ev[11]=c.w;
                ev[12]=d.x; ev[13]=d.y; ev[14]=d.z; ev[15]=d.w;
            }
            {
                const float4* kp = (const float4*)(ks + m*164 + h*20);
                float4 a = kp[0], b = kp[1], c = kp[2], d = kp[3];
                kv[0]=a.x; kv[1]=a.y; kv[2]=a.z; kv[3]=a.w;
                kv[4]=b.x; kv[5]=b.y; kv[6]=b.z; kv[7]=b.w;
                kv[8]=c.x; kv[9]=c.y; kv[10]=c.z; kv[11]=c.w;
                kv[12]=d.x; kv[13]=d.y; kv[14]=d.z; kv[15]=d.w;
            }
            // four accumulator chains (2 bias, 2 qk) to shorten latency
            float a0 = baeR, a1 = 0.f, b0 = 0.f, b1 = 0.f;
            #pragma unroll
            for (int e = 0; e < 16; e += 2) {
                a0 += ev[e]   * waeR[e];
                a1 += ev[e+1] * waeR[e+1];
                b0 += qr[e]   * kv[e];
                b1 += qr[e+1] * kv[e+1];
            }
            float logit = (a0 + a1) + (b0 + b1);
            float w = mrow[m] ? __expf(logit) : 0.0f;
            den += w;
            #pragma unroll
            for (int e = 0; e < 16; e++) S[e] += w * ev[e];
            {
                const float4* vp = (const float4*)(vs + m*164 + h*20);
                float4 a = vp[0], b = vp[1], c = vp[2], d = vp[3];
                av[0]+=w*a.x;  av[1]+=w*a.y;  av[2]+=w*a.z;  av[3]+=w*a.w;
                av[4]+=w*b.x;  av[5]+=w*b.y;  av[6]+=w*b.z;  av[7]+=w*b.w;
                av[8]+=w*c.x;  av[9]+=w*c.y;  av[10]+=w*c.z; av[11]+=w*c.w;
                av[12]+=w*d.x; av[13]+=w*d.y; av[14]+=w*d.z; av[15]+=w*d.w;
            }
        }
    }

    // write partials (deterministic; combined in k_out)
    float* Sp = g_Sp  + ((size_t)bs*NN + n)*128 + h*16;
    float* Ap = g_avp + ((size_t)bs*NN + n)*128 + h*16;
    #pragma unroll
    for (int i = 0; i < 4; i++) {
        *(float4*)(Sp + i*4) = make_float4(S[i*4], S[i*4+1], S[i*4+2], S[i*4+3]);
        *(float4*)(Ap + i*4) = make_float4(av[i*4], av[i*4+1], av[i*4+2], av[i*4+3]);
    }
    g_dnp[((size_t)bs*NN + n)*8 + h] = den;
}

// ================= E: combine partials + edge term + Wo + residual ======
__global__ __launch_bounds__(128) void k_out(
    const float* __restrict__ x,
    const float* __restrict__ Wve, const float* __restrict__ bve,
    const float* __restrict__ Wo, const float* __restrict__ bo,
    float* __restrict__ out)
{
    __shared__ float Ss[128], attS[128], denS[8];
    int nq = blockIdx.x, c = threadIdx.x, hh = c >> 4;
    float s = 0.f, a = 0.f;
    #pragma unroll
    for (int p = 0; p < MSPLIT; p++) {
        s += g_Sp [((size_t)p*NN + nq)*128 + c];
        a += g_avp[((size_t)p*NN + nq)*128 + c];
    }
    Ss[c] = s;
    if (c < 8) {
        float dn = 0.f;
        #pragma unroll
        for (int p = 0; p < MSPLIT; p++) dn += g_dnp[((size_t)p*NN + nq)*8 + c];
        denS[c] = dn;
    }
    __syncthreads();
    float acc = a;
    #pragma unroll
    for (int e = 0; e < 16; e++) acc += Ss[hh*16 + e] * Wve[e*128 + c];
    float att = acc / denS[hh] + bve[c];
    attS[c] = att;
    __syncthreads();
    float o = bo[c];
    #pragma unroll 8
    for (int j = 0; j < 128; j++) o += attS[j] * Wo[j*128 + c];
    out[(size_t)nq*128 + c] = x[(size_t)nq*128 + c] + o;
}

// ================= launcher =================
extern "C" void kernel_launch(void* const* d_in, const int* in_sizes, int n_in,
                              void* d_out, int out_size)
{
    const float* x     = (const float*)d_in[0];
    const float* edge  = (const float*)d_in[1];
    const int*   mask  = (const int*)  d_in[2];
    const float* Wq    = (const float*)d_in[3];
    const float* bq    = (const float*)d_in[4];
    const float* Wk    = (const float*)d_in[5];
    const float* bk    = (const float*)d_in[6];
    const float* Wv    = (const float*)d_in[7];
    const float* bv    = (const float*)d_in[8];
    const float* Wae   = (const float*)d_in[9];
    const float* bae   = (const float*)d_in[10];
    const float* Wve   = (const float*)d_in[11];
    const float* bve   = (const float*)d_in[12];
    const float* Wo    = (const float*)d_in[13];
    const float* bo    = (const float*)d_in[14];
    const float* gamma = (const float*)d_in[15];
    const float* beta  = (const float*)d_in[16];
    float* out = (float*)d_out;

    static int smem_set = 0;
    if (!smem_set) {
        cudaFuncSetAttribute(k_fused, cudaFuncAttributeMaxDynamicSharedMemorySize,
                             SM_FLOATS * 4);
        smem_set = 1;
    }

    k_qkv<<<256, 128>>>(x, Wq, bq, Wk, bk, Wv, bv, gamma, beta);
    k_fused<<<128, 256, SM_FLOATS * 4>>>(edge, mask, Wae, bae);
    k_out<<<1024, 128>>>(x, Wve, bve, Wo, bo, out);
}

// round 13
// speedup vs baseline: 2.3114x; 1.2888x over previous
#include <cuda_runtime.h>
#include <math.h>

#define NN 1024
#define HEADS 8
#define EDIM 16
#define TN 32          // n-tile per block (fused)
#define TM 32          // m chunk staged per iteration
#define MSPLIT 4       // m-range split across blocks
#define CHUNKS 8       // chunks per block: TM*CHUNKS = 256 m

typedef unsigned long long ull;

// -------- device scratch (allocation-free) --------
__device__ float g_q[NN*128];
__device__ float g_k[NN*128];
__device__ float g_v[NN*128];
__device__ float g_Sp [MSPLIT*(size_t)NN*128];   // partial S  per m-split
__device__ float g_avp[MSPLIT*(size_t)NN*128];   // partial av per m-split
__device__ float g_dnp[MSPLIT*NN*HEADS];         // partial den

// ---- packed f32x2 helpers (sm_103a) ----
__device__ __forceinline__ ull pk2(float lo, float hi) {
    ull r; asm("mov.b64 %0, {%1,%2};" : "=l"(r) : "f"(lo), "f"(hi)); return r;
}
__device__ __forceinline__ void upk2(float& lo, float& hi, ull v) {
    asm("mov.b64 {%0,%1}, %2;" : "=f"(lo), "=f"(hi) : "l"(v));
}
__device__ __forceinline__ ull fma2(ull a, ull b, ull c) {
    ull d; asm("fma.rn.f32x2 %0, %1, %2, %3;" : "=l"(d) : "l"(a), "l"(b), "l"(c)); return d;
}
__device__ __forceinline__ ull add2(ull a, ull b) {
    ull d; asm("add.rn.f32x2 %0, %1, %2;" : "=l"(d) : "l"(a), "l"(b)); return d;
}

// smem layout for k_fused (float offsets)
#define K_OFF 0                       // ks[32][164]   (m*164 + h*20 + d)
#define V_OFF 5248                    // vs[32][164]
#define E_OFF 10496                   // es[32 n][516] (n*516 + m*16 + e)
#define M_OFF 27008                   // ms[32 n][33]  ints
#define SM_FLOATS (27008 + 1056)      // 28064 floats = 112256 B

// ============ A: fused LayerNorm + QKV GEMM ============
// grid 128 (8 nodes/block), 384 threads (one output column each: 0-127 q,
// 128-255 k, 256-383 v). Weights staged in smem in 32-row chunks.
#define QKV_SM_FLOATS (1024 + 32*384)   // hs[8][128] + ws[32][384] = 13312 fl

__global__ __launch_bounds__(384) void k_qkv2(
    const float* __restrict__ x,
    const float* __restrict__ Wq, const float* __restrict__ bq,
    const float* __restrict__ Wk, const float* __restrict__ bk,
    const float* __restrict__ Wv, const float* __restrict__ bv,
    const float* __restrict__ gamma, const float* __restrict__ beta)
{
    extern __shared__ float sm2[];
    float* hs = sm2;            // [8][128]
    float* ws = sm2 + 1024;     // [32][384]
    int tid = threadIdx.x;
    int n0 = blockIdx.x * 8;
    int w = tid >> 5, lane = tid & 31;

    if (w < 8) {   // LayerNorm: warp w handles node n0+w
        float4 xa = ((const float4*)(x + (size_t)(n0 + w)*128))[lane];
        float s  = xa.x + xa.y + xa.z + xa.w;
        float s2 = xa.x*xa.x + xa.y*xa.y + xa.z*xa.z + xa.w*xa.w;
        #pragma unroll
        for (int o = 16; o; o >>= 1) {
            s  += __shfl_xor_sync(0xffffffffu, s,  o);
            s2 += __shfl_xor_sync(0xffffffffu, s2, o);
        }
        float mu  = s * (1.0f/128.0f);
        float var = s2 * (1.0f/128.0f) - mu*mu;
        float rs  = rsqrtf(var + 1e-5f);
        float4 gv = ((const float4*)gamma)[lane];
        float4 bt = ((const float4*)beta)[lane];
        float4 hv;
        hv.x = (xa.x - mu)*rs*gv.x + bt.x;
        hv.y = (xa.y - mu)*rs*gv.y + bt.y;
        hv.z = (xa.z - mu)*rs*gv.z + bt.z;
        hv.w = (xa.w - mu)*rs*gv.w + bt.w;
        ((float4*)(hs + w*128))[lane] = hv;
    }

    int col = tid, mtx = col >> 7, wcol = col & 127;
    const float* Wm = (mtx == 0) ? Wq : (mtx == 1) ? Wk : Wv;
    float bias = (mtx == 0) ? bq[wcol] : (mtx == 1) ? bk[wcol] : bv[wcol];
    float acc[8];
    #pragma unroll
    for (int i = 0; i < 8; i++) acc[i] = 0.f;

    #pragma unroll
    for (int kc = 0; kc < 4; kc++) {
        int j0 = kc * 32;
        __syncthreads();
        #pragma unroll
        for (int i = 0; i < 32; i++)
            ws[i*384 + tid] = Wm[(size_t)(j0 + i)*128 + wcol];
        __syncthreads();
        #pragma unroll
        for (int jg = 0; jg < 8; jg++) {
            int j = j0 + jg*4;
            float4 h0 = *(const float4*)(hs + 0*128 + j);
            float4 h1 = *(const float4*)(hs + 1*128 + j);
            float4 h2 = *(const float4*)(hs + 2*128 + j);
            float4 h3 = *(const float4*)(hs + 3*128 + j);
            float4 h4 = *(const float4*)(hs + 4*128 + j);
            float4 h5 = *(const float4*)(hs + 5*128 + j);
            float4 h6 = *(const float4*)(hs + 6*128 + j);
            float4 h7 = *(const float4*)(hs + 7*128 + j);
            float w0 = ws[(jg*4+0)*384 + tid];
            float w1 = ws[(jg*4+1)*384 + tid];
            float w2 = ws[(jg*4+2)*384 + tid];
            float w3 = ws[(jg*4+3)*384 + tid];
            acc[0] += h0.x*w0 + h0.y*w1 + h0.z*w2 + h0.w*w3;
            acc[1] += h1.x*w0 + h1.y*w1 + h1.z*w2 + h1.w*w3;
            acc[2] += h2.x*w0 + h2.y*w1 + h2.z*w2 + h2.w*w3;
            acc[3] += h3.x*w0 + h3.y*w1 + h3.z*w2 + h3.w*w3;
            acc[4] += h4.x*w0 + h4.y*w1 + h4.z*w2 + h4.w*w3;
            acc[5] += h5.x*w0 + h5.y*w1 + h5.z*w2 + h5.w*w3;
            acc[6] += h6.x*w0 + h6.y*w1 + h6.z*w2 + h6.w*w3;
            acc[7] += h7.x*w0 + h7.y*w1 + h7.z*w2 + h7.w*w3;
        }
    }
    float scale = (mtx == 0) ? 0.25f : 1.0f;   // q pre-scaled by 1/sqrt(dk)
    float* dst = (mtx == 0) ? g_q : (mtx == 1) ? g_k : g_v;
    #pragma unroll
    for (int nn = 0; nn < 8; nn++)
        dst[(size_t)(n0 + nn)*128 + wcol] = (acc[nn] + bias) * scale;
}

// ============ FUSED: logits + exp + S/den/av (packed f32x2) ============
// grid 128: bn = b&31 (32-n tile), bs = b>>5 (m-split of 256).
// 256 threads: h = tid&7, nl = tid>>3. Thread owns (n,h); w stays in regs.
__global__ __launch_bounds__(256) void k_fused(
    const float* __restrict__ edge, const int* __restrict__ mask,
    const float* __restrict__ Wae, const float* __restrict__ bae)
{
    extern __shared__ float sm[];
    float* ks = sm + K_OFF;
    float* vs = sm + V_OFF;
    float* es = sm + E_OFF;
    int*   ms = (int*)(sm + M_OFF);

    int tid = threadIdx.x;
    int h = tid & 7, nl = tid >> 3;
    int bn = blockIdx.x & 31, bs = blockIdx.x >> 5;
    int n0 = bn * TN;
    int n  = n0 + nl;

    ull qr2[8];
    {
        const ulonglong2* qp = (const ulonglong2*)(g_q + (size_t)n*128 + h*16);
        ulonglong2 a = qp[0], b = qp[1], c = qp[2], d = qp[3];
        qr2[0]=a.x; qr2[1]=a.y; qr2[2]=b.x; qr2[3]=b.y;
        qr2[4]=c.x; qr2[5]=c.y; qr2[6]=d.x; qr2[7]=d.y;
    }
    ull wae2[8];
    #pragma unroll
    for (int e = 0; e < 8; e++) wae2[e] = pk2(Wae[(2*e)*8 + h], Wae[(2*e+1)*8 + h]);
    float baeR = bae[h];

    ull S2[8], av2[8];
    float den = 0.f;
    #pragma unroll
    for (int i = 0; i < 8; i++) { S2[i] = 0ull; av2[i] = 0ull; }

    for (int ch = 0; ch < CHUNKS; ch++) {
        int m0 = bs*256 + ch*TM;
        __syncthreads();
        // stage edge (32n x 32m x 16e)
        #pragma unroll
        for (int i = 0; i < 16; i++) {
            int f = tid + i*256;
            int nn = f >> 7, rem = f & 127;
            float4 val = ((const float4*)(edge + ((size_t)(n0+nn)*NN + m0)*16))[rem];
            *(float4*)(es + nn*516 + rem*4) = val;
        }
        // stage k,v (32m x 128), h-stride 20, m-stride 164
        #pragma unroll
        for (int i = 0; i < 4; i++) {
            int f = tid + i*256;
            int mm = f >> 5, c4 = f & 31;
            int hh = c4 >> 2, dd = c4 & 3;
            *(float4*)(ks + mm*164 + hh*20 + dd*4) =
                ((const float4*)(g_k + (size_t)(m0+mm)*128))[c4];
            *(float4*)(vs + mm*164 + hh*20 + dd*4) =
                ((const float4*)(g_v + (size_t)(m0+mm)*128))[c4];
        }
        // stage mask
        #pragma unroll
        for (int i = 0; i < 4; i++) {
            int f = tid + i*256;
            int nn = f >> 5, mm = f & 31;
            ms[nn*33 + mm] = mask[(size_t)(n0+nn)*NN + m0 + mm];
        }
        __syncthreads();

        const float* ep_base = es + nl*516;
        const int*   mrow    = ms + nl*33;
        #pragma unroll 2
        for (int m = 0; m < TM; m++) {
            ull ev2[8], kv2[8], vv2[8];
            {
                const ulonglong2* ep = (const ulonglong2*)(ep_base + m*16);
                ulonglong2 a = ep[0], b = ep[1], c = ep[2], d = ep[3];
                ev2[0]=a.x; ev2[1]=a.y; ev2[2]=b.x; ev2[3]=b.y;
                ev2[4]=c.x; ev2[5]=c.y; ev2[6]=d.x; ev2[7]=d.y;
            }
            {
                const ulonglong2* kp = (const ulonglong2*)(ks + m*164 + h*20);
                ulonglong2 a = kp[0], b = kp[1], c = kp[2], d = kp[3];
                kv2[0]=a.x; kv2[1]=a.y; kv2[2]=b.x; kv2[3]=b.y;
                kv2[4]=c.x; kv2[5]=c.y; kv2[6]=d.x; kv2[7]=d.y;
            }
            // bias dot (2 chains) + qk dot (2 chains), packed
            ull t0 = 0ull, t1 = 0ull, u0 = 0ull, u1 = 0ull;
            #pragma unroll
            for (int e = 0; e < 8; e += 2) {
                t0 = fma2(ev2[e],   wae2[e],   t0);
                t1 = fma2(ev2[e+1], wae2[e+1], t1);
                u0 = fma2(qr2[e],   kv2[e],    u0);
                u1 = fma2(qr2[e+1], kv2[e+1],  u1);
            }
            ull su = add2(add2(t0, t1), add2(u0, u1));
            float lo, hi; upk2(lo, hi, su);
            float logit = lo + hi + baeR;
            float wv = mrow[m] ? __expf(logit) : 0.0f;
            den += wv;
            ull w2 = pk2(wv, wv);
            {
                const ulonglong2* vp = (const ulonglong2*)(vs + m*164 + h*20);
                ulonglong2 a = vp[0], b = vp[1], c = vp[2], d = vp[3];
                vv2[0]=a.x; vv2[1]=a.y; vv2[2]=b.x; vv2[3]=b.y;
                vv2[4]=c.x; vv2[5]=c.y; vv2[6]=d.x; vv2[7]=d.y;
            }
            #pragma unroll
            for (int i = 0; i < 8; i++) {
                S2[i]  = fma2(w2, ev2[i], S2[i]);
                av2[i] = fma2(w2, vv2[i], av2[i]);
            }
        }
    }

    // write partials (deterministic; combined in k_out)
    ulonglong2* Sp = (ulonglong2*)(g_Sp  + ((size_t)bs*NN + n)*128 + h*16);
    ulonglong2* Ap = (ulonglong2*)(g_avp + ((size_t)bs*NN + n)*128 + h*16);
    #pragma unroll
    for (int i = 0; i < 4; i++) {
        ulonglong2 sv; sv.x = S2[2*i];  sv.y = S2[2*i+1];  Sp[i] = sv;
        ulonglong2 av; av.x = av2[2*i]; av.y = av2[2*i+1]; Ap[i] = av;
    }
    g_dnp[((size_t)bs*NN + n)*8 + h] = den;
}

// ============ E: combine partials + edge term + Wo + residual ============
__global__ __launch_bounds__(128) void k_out(
    const float* __restrict__ x,
    const float* __restrict__ Wve, const float* __restrict__ bve,
    const float* __restrict__ Wo, const float* __restrict__ bo,
    float* __restrict__ out)
{
    __shared__ float Ss[128], attS[128], denS[8];
    int nq = blockIdx.x, c = threadIdx.x, hh = c >> 4;
    float s = 0.f, a = 0.f;
    #pragma unroll
    for (int p = 0; p < MSPLIT; p++) {
        s += g_Sp [((size_t)p*NN + nq)*128 + c];
        a += g_avp[((size_t)p*NN + nq)*128 + c];
    }
    Ss[c] = s;
    if (c < 8) {
        float dn = 0.f;
        #pragma unroll
        for (int p = 0; p < MSPLIT; p++) dn += g_dnp[((size_t)p*NN + nq)*8 + c];
        denS[c] = dn;
    }
    __syncthreads();
    float acc = a;
    #pragma unroll
    for (int e = 0; e < 16; e++) acc += Ss[hh*16 + e] * Wve[e*128 + c];
    float att = acc / denS[hh] + bve[c];
    attS[c] = att;
    __syncthreads();
    float o = bo[c];
    #pragma unroll 8
    for (int j = 0; j < 128; j++) o += attS[j] * Wo[j*128 + c];
    out[(size_t)nq*128 + c] = x[(size_t)nq*128 + c] + o;
}

// ================= launcher =================
extern "C" void kernel_launch(void* const* d_in, const int* in_sizes, int n_in,
                              void* d_out, int out_size)
{
    const float* x     = (const float*)d_in[0];
    const float* edge  = (const float*)d_in[1];
    const int*   mask  = (const int*)  d_in[2];
    const float* Wq    = (const float*)d_in[3];
    const float* bq    = (const float*)d_in[4];
    const float* Wk    = (const float*)d_in[5];
    const float* bk    = (const float*)d_in[6];
    const float* Wv    = (const float*)d_in[7];
    const float* bv    = (const float*)d_in[8];
    const float* Wae   = (const float*)d_in[9];
    const float* bae   = (const float*)d_in[10];
    const float* Wve   = (const float*)d_in[11];
    const float* bve   = (const float*)d_in[12];
    const float* Wo    = (const float*)d_in[13];
    const float* bo    = (const float*)d_in[14];
    const float* gamma = (const float*)d_in[15];
    const float* beta  = (const float*)d_in[16];
    float* out = (float*)d_out;

    cudaFuncSetAttribute(k_qkv2, cudaFuncAttributeMaxDynamicSharedMemorySize,
                         QKV_SM_FLOATS * 4);
    cudaFuncSetAttribute(k_fused, cudaFuncAttributeMaxDynamicSharedMemorySize,
                         SM_FLOATS * 4);

    k_qkv2<<<128, 384, QKV_SM_FLOATS * 4>>>(x, Wq, bq, Wk, bk, Wv, bv, gamma, beta);
    k_fused<<<128, 256, SM_FLOATS * 4>>>(edge, mask, Wae, bae);
    k_out<<<1024, 128>>>(x, Wve, bve, Wo, bo, out);
}